// round 12
// baseline (speedup 1.0000x reference)
#include <cuda_runtime.h>
#include <cuda_bf16.h>
#include <cstddef>

#define EPSF 0.01f
#define NU 256
#define NB 64
#define TS 2048

// Module-load-time scratch (no runtime allocation)
__device__ float g_xu[(size_t)NB * TS * NU];   // x@U + b, [b][t][u]
__device__ float g_AeT[NU * NU];               // EPS*A, transposed
__device__ float g_WT [NU * NU];               // W, transposed

// ---------------- packed fp32x2 helpers ----------------
static __device__ __forceinline__ unsigned long long fma2(unsigned long long a,
                                                          unsigned long long b,
                                                          unsigned long long c) {
    unsigned long long d;
    asm("fma.rn.f32x2 %0, %1, %2, %3;" : "=l"(d) : "l"(a), "l"(b), "l"(c));
    return d;
}
static __device__ __forceinline__ unsigned long long add2(unsigned long long a,
                                                          unsigned long long b) {
    unsigned long long d;
    asm("add.rn.f32x2 %0, %1, %2;" : "=l"(d) : "l"(a), "l"(b));
    return d;
}
static __device__ __forceinline__ unsigned long long pk2(float lo, float hi) {
    unsigned long long d;
    asm("mov.b64 %0, {%1, %2};" : "=l"(d) : "f"(lo), "f"(hi));
    return d;
}
static __device__ __forceinline__ void upk2(unsigned long long v, float& lo, float& hi) {
    asm("mov.b64 {%0, %1}, %2;" : "=f"(lo), "=f"(hi) : "l"(v));
}
static __device__ __forceinline__ unsigned su32(const void* p) {
    unsigned r;
    asm("{ .reg .u64 t; cvta.to.shared.u64 t, %1; cvt.u32.u64 %0, t; }" : "=r"(r) : "l"(p));
    return r;
}
static __device__ __forceinline__ void mbar_init(unsigned m, unsigned cnt) {
    asm volatile("mbarrier.init.shared.b64 [%0], %1;" :: "r"(m), "r"(cnt) : "memory");
}
static __device__ __forceinline__ void mbar_expect(unsigned m, unsigned bytes) {
    asm volatile("mbarrier.arrive.expect_tx.shared.b64 _, [%0], %1;" :: "r"(m), "r"(bytes) : "memory");
}
static __device__ __forceinline__ void mbar_wait(unsigned m, unsigned phase) {
    unsigned done;
    asm volatile(
        "{\n\t.reg .pred p;\n\t"
        "mbarrier.try_wait.parity.acquire.cluster.shared::cta.b64 p, [%1], %2;\n\t"
        "selp.b32 %0, 1, 0, p;\n\t}"
        : "=r"(done) : "r"(m), "r"(phase) : "memory");
    while (!done) {
        asm volatile(
            "{\n\t.reg .pred p;\n\t"
            "mbarrier.try_wait.parity.acquire.cluster.shared::cta.b64 p, [%1], %2, 0x989680;\n\t"
            "selp.b32 %0, 1, 0, p;\n\t}"
            : "=r"(done) : "r"(m), "r"(phase) : "memory");
    }
}
static __device__ __forceinline__ void st_async_b64(unsigned raddr, unsigned long long v,
                                                    unsigned rmbar) {
    asm volatile("st.async.shared::cluster.mbarrier::complete_tx::bytes.b64 [%0], %1, [%2];"
                 :: "r"(raddr), "l"(v), "r"(rmbar) : "memory");
}

// ---------------- kernel 1: build weight matrices ----------------
__global__ void prep_kernel(const float* __restrict__ C, const float* __restrict__ B) {
    int u = blockIdx.x;
    int k = threadIdx.x;
    float dg = (u == k) ? 0.01f : 0.0f;
    g_AeT[u * NU + k] = EPSF * (B[k * NU + u] - 0.6f * B[u * NU + k] - dg);
    g_WT [u * NU + k] =        (C[k * NU + u] - 0.6f * C[u * NU + k] - dg);
}

// ---------------- kernel 2: xu = X @ U + bias ----------------
__global__ __launch_bounds__(256) void xu_kernel(const float* __restrict__ X,
                                                 const float* __restrict__ U,
                                                 const float* __restrict__ bias) {
    __shared__ __align__(16) float Xs[32][132];
    __shared__ __align__(16) float Us[32][132];

    int tid = threadIdx.x;
    int m0 = blockIdx.x * 128;
    int n0 = blockIdx.y * 128;
    int tx = tid & 15;
    int ty = tid >> 4;

    unsigned long long acc[8][4];
#pragma unroll
    for (int i = 0; i < 8; i++)
#pragma unroll
        for (int j = 0; j < 4; j++) acc[i][j] = 0ULL;

    for (int kt = 0; kt < 256; kt += 32) {
#pragma unroll
        for (int i = 0; i < 4; i++) {
            int f = tid + i * 256;
            int m = f >> 3;
            int k4 = (f & 7) * 4;
            float4 v = *(const float4*)&X[(size_t)(m0 + m) * 256 + kt + k4];
            Xs[k4 + 0][m] = v.x;
            Xs[k4 + 1][m] = v.y;
            Xs[k4 + 2][m] = v.z;
            Xs[k4 + 3][m] = v.w;
        }
#pragma unroll
        for (int i = 0; i < 4; i++) {
            int f = tid + i * 256;
            int k = f >> 5;
            int n4 = (f & 31) * 4;
            float4 v = *(const float4*)&U[(size_t)(kt + k) * 256 + n0 + n4];
            *(float4*)&Us[k][n4] = v;
        }
        __syncthreads();

#pragma unroll
        for (int kk = 0; kk < 32; kk++) {
            float a[8];
            *(float4*)&a[0] = *(const float4*)&Xs[kk][ty * 8];
            *(float4*)&a[4] = *(const float4*)&Xs[kk][ty * 8 + 4];
            ulonglong2 b01 = *(const ulonglong2*)&Us[kk][tx * 8];
            ulonglong2 b23 = *(const ulonglong2*)&Us[kk][tx * 8 + 4];
#pragma unroll
            for (int mi = 0; mi < 8; mi++) {
                unsigned long long ad = pk2(a[mi], a[mi]);
                acc[mi][0] = fma2(ad, b01.x, acc[mi][0]);
                acc[mi][1] = fma2(ad, b01.y, acc[mi][1]);
                acc[mi][2] = fma2(ad, b23.x, acc[mi][2]);
                acc[mi][3] = fma2(ad, b23.y, acc[mi][3]);
            }
        }
        __syncthreads();
    }

    float bv[8];
#pragma unroll
    for (int j = 0; j < 8; j++) bv[j] = bias[n0 + tx * 8 + j];
#pragma unroll
    for (int mi = 0; mi < 8; mi++) {
        float* orow = &g_xu[(size_t)(m0 + ty * 8 + mi) * 256 + n0 + tx * 8];
#pragma unroll
        for (int ni = 0; ni < 4; ni++) {
            float lo, hi;
            upk2(acc[mi][ni], lo, hi);
            float2 v = make_float2(lo + bv[2 * ni], hi + bv[2 * ni + 1]);
            *(float2*)&orow[2 * ni] = v;
        }
    }
}

// ---------------- kernel 3: the recurrence (warp-specialized, 1 sync/step) ----
// 32 clusters x 4 CTAs. CTA rank r owns units [64r,64r+64); weights in regs.
// h per buffer: [batch][k-pair u64] (2 KB), triple buffered.
// Warps split by source rank of their k-range (ks). LOCAL warps (ks==rank) are
// the consumers: they order their own STS via bar.sync(1,128), compute on local
// h, then after the single __syncthreads run the epilogue. REMOTE warps park on
// their per-source mbarrier (data gate), FMA on arrival, STS red, sync, loop —
// the consumer epilogue overlaps their mbar wait. red_s parity double-buffered.
__global__ void __launch_bounds__(512, 1) __cluster_dims__(4, 1, 1)
rec_kernel(float* __restrict__ out) {
    __shared__ __align__(16) unsigned long long h_s[3][2][128];       // 6 KB
    __shared__ __align__(16) unsigned long long red_s[2][2][4][64];   // [par][mat][ks][unit] 8 KB
    __shared__ __align__(8)  unsigned long long mbars[12];            // [buf][src]

    int tid  = threadIdx.x;
    int lane = tid & 31;
    int wid  = tid >> 5;             // 16 warps
    int mat  = wid >> 3;             // 0 = A, 1 = W
    int ks   = (wid >> 1) & 3;       // source rank of this warp's k-range
    int usub = wid & 1;
    int unit = usub * 32 + lane;     // 0..63 within CTA slice
    unsigned rank;
    asm("mov.u32 %0, %%cluster_ctarank;" : "=r"(rank));
    int bg  = (int)(blockIdx.x >> 2);
    int ug  = (int)rank * 64 + unit;
    int kp0 = ks * 32;

    bool is_local = (ks == (int)rank);                        // warp-uniform
    bool is_armer = !is_local && mat == 0 && usub == 0 && lane == 0;

    // Weight slice in registers as native k-pairs.
    unsigned long long wD[32];
    {
        const float* wsrc = (mat == 0) ? g_AeT : g_WT;
        const unsigned long long* wp =
            (const unsigned long long*)(wsrc + (size_t)ug * NU) + kp0;
#pragma unroll
        for (int i = 0; i < 32; i++) wD[i] = wp[i];
    }

    // Init: zero buffer 0, init per-source tx mbarriers, pre-arm bufs 1, 2.
    if (tid < 256) h_s[0][tid >> 7][tid & 127] = 0ULL;
    unsigned mb = su32(&mbars[0]);
    if (tid == 0) {
#pragma unroll
        for (int i = 0; i < 12; i++) mbar_init(mb + 8u * i, 1);
#pragma unroll
        for (int s = 0; s < 4; s++) {
            if (s != (int)rank) {
                mbar_expect(mb + (1 * 4 + s) * 8u, 512);
                mbar_expect(mb + (2 * 4 + s) * 8u, 512);
            }
        }
    }
    __syncthreads();
    asm volatile("barrier.cluster.arrive.aligned;" ::: "memory");
    asm volatile("barrier.cluster.wait.aligned;" ::: "memory");

    // Consumer identity: local-warp threads, (batch cb = mat, unit cu = unit)
    int cb  = mat;
    int cu  = unit;
    int cug = (int)rank * 64 + cu;
    const float* xu_p = g_xu + ((size_t)(bg * 2 + cb) * TS) * NU + cug;
    float* out_p      = out  + ((size_t)(bg * 2 + cb) * TS) * NU + cug;
    unsigned pair_off = (unsigned)cb * 1024u + (unsigned)rank * 256u + (unsigned)(cu >> 1) * 8u;

    // Remote base addresses for the 3 OTHER cluster ranks
    unsigned ra3[3];
    unsigned h0 = su32(&h_s[0][0][0]);
    unsigned mdel = mb - h0;
    {
        int j = 0;
#pragma unroll
        for (int r = 0; r < 4; r++) {
            if (r != (int)rank) {
                asm("mapa.shared::cluster.u32 %0, %1, %2;" : "=r"(ra3[j]) : "r"(h0), "r"(r));
                j++;
            }
        }
    }

    unsigned ph0 = 0, ph1 = 0, ph2 = 0;
    float hold = 0.0f;     // loop-carried h (consumer threads)

    // xu prefetch pipeline (consumers): xu_nxt holds xu[t] at top of step t.
    float xu_nxt = 0.0f;
    if (is_local) xu_nxt = __ldg(xu_p);

#define DO_STEP(RB, WB, PH, DOWAIT, T)                                              \
    {                                                                               \
        float xu_v = 0.0f;                                                          \
        if (!is_local) {                                                            \
            if (DOWAIT) { mbar_wait(mb + ((RB) * 4 + ks) * 8u, (PH)); }             \
            if (is_armer) mbar_expect(mb + ((RB) * 4 + ks) * 8u, 512);              \
        } else {                                                                    \
            asm volatile("bar.sync 1, 128;" ::: "memory");  /* order local STS */   \
            xu_v = xu_nxt;                                                          \
            if ((T) + 1 < TS) xu_nxt = __ldg(xu_p + (size_t)((T) + 1) * NU);        \
        }                                                                           \
        unsigned long long a00 = 0, a01 = 0, a10 = 0, a11 = 0;                      \
        {                                                                           \
            const ulonglong2* hb0 = (const ulonglong2*)&h_s[RB][0][kp0];            \
            const ulonglong2* hb1 = (const ulonglong2*)&h_s[RB][1][kp0];            \
            _Pragma("unroll")                                                       \
            for (int i = 0; i < 16; i++) {                                          \
                ulonglong2 v0 = hb0[i];                                             \
                ulonglong2 v1 = hb1[i];                                             \
                a00 = fma2(wD[2 * i + 0], v0.x, a00);                               \
                a01 = fma2(wD[2 * i + 1], v0.y, a01);                               \
                a10 = fma2(wD[2 * i + 0], v1.x, a10);                               \
                a11 = fma2(wD[2 * i + 1], v1.y, a11);                               \
            }                                                                       \
        }                                                                           \
        {                                                                           \
            unsigned long long s0 = add2(a00, a01);                                 \
            unsigned long long s1 = add2(a10, a11);                                 \
            float l0, hh0, l1, hh1;                                                 \
            upk2(s0, l0, hh0);                                                      \
            upk2(s1, l1, hh1);                                                      \
            red_s[(T) & 1][mat][ks][unit] = pk2(l0 + hh0, l1 + hh1);                \
        }                                                                           \
        __syncthreads();                                                            \
        if (is_local) {                                                             \
            /* W-part first so tanh starts ASAP */                                  \
            float sW = 0.0f;                                                        \
            _Pragma("unroll")                                                       \
            for (int kss = 0; kss < 4; kss++)                                       \
                sW += ((const float*)&red_s[(T) & 1][1][kss][cu])[cb];              \
            float th = tanhf(sW + xu_v);                                            \
            float sA = 0.0f;                                                        \
            _Pragma("unroll")                                                       \
            for (int kss = 0; kss < 4; kss++)                                       \
                sA += ((const float*)&red_s[(T) & 1][0][kss][cu])[cb];              \
            float hnew = hold + sA + EPSF * th;                                     \
            hold = hnew;                                                            \
            float other = __shfl_xor_sync(0xFFFFFFFFu, hnew, 1);                    \
            unsigned long long val = (cu & 1) ? pk2(other, hnew) : pk2(hnew, other);\
            unsigned doff = (unsigned)(WB) * 2048u + pair_off;                      \
            unsigned moff = mdel + ((WB) * 4 + (int)rank) * 8u;                     \
            if (!(cu & 1)) {                                                        \
                st_async_b64(ra3[0] + doff, val, ra3[0] + moff);                    \
                st_async_b64(ra3[1] + doff, val, ra3[1] + moff);                    \
                st_async_b64(ra3[2] + doff, val, ra3[2] + moff);                    \
                h_s[WB][cb][(int)rank * 32 + (cu >> 1)] = val;  /* local STS */     \
            }                                                                       \
            out_p[(size_t)(T) * NU] = hnew;                                         \
        }                                                                           \
    }

    // step 0 (reads pre-zeroed buffer 0, no wait; arms buf0's source barriers)
    DO_STEP(0, 1, ph0, false, 0);
    int t = 1;
    while (t < TS) {
        DO_STEP(1, 2, ph1, true, t); ph1 ^= 1; t++;
        if (t < TS) { DO_STEP(2, 0, ph2, true, t); ph2 ^= 1; t++; }
        if (t < TS) { DO_STEP(0, 1, ph0, true, t); ph0 ^= 1; t++; }
    }
#undef DO_STEP

    // Drain: final sends (t=2047) filled buf 2; wait for those arrivals so no
    // CTA exits while peers' remote stores into its smem are in flight.
    __syncthreads();
    if (tid == 0) {
#pragma unroll
        for (int s = 0; s < 4; s++)
            if (s != (int)rank) mbar_wait(mb + (2 * 4 + s) * 8u, ph2);
    }
    __syncthreads();
    asm volatile("barrier.cluster.arrive.aligned;" ::: "memory");
    asm volatile("barrier.cluster.wait.aligned;" ::: "memory");
}

extern "C" void kernel_launch(void* const* d_in, const int* in_sizes, int n_in,
                              void* d_out, int out_size) {
    const float* x = (const float*)d_in[0];
    const float* C = (const float*)d_in[1];
    const float* B = (const float*)d_in[2];
    const float* U = (const float*)d_in[3];
    const float* b = (const float*)d_in[4];
    float* out = (float*)d_out;

    prep_kernel<<<NU, NU>>>(C, B);
    xu_kernel<<<dim3((NB * TS) / 128, NU / 128), 256>>>(x, U, b);
    rec_kernel<<<128, 512>>>(out);
}

// round 13
// speedup vs baseline: 1.0166x; 1.0166x over previous
#include <cuda_runtime.h>
#include <cuda_bf16.h>
#include <cstddef>

#define EPSF 0.01f
#define NU 256
#define NB 64
#define TS 2048

// Module-load-time scratch (no runtime allocation)
__device__ float g_xu[(size_t)NB * TS * NU];   // x@U + b, [b][t][u]
__device__ float g_AeT[NU * NU];               // EPS*A, transposed
__device__ float g_WT [NU * NU];               // W, transposed

// ---------------- packed fp32x2 helpers ----------------
static __device__ __forceinline__ unsigned long long fma2(unsigned long long a,
                                                          unsigned long long b,
                                                          unsigned long long c) {
    unsigned long long d;
    asm("fma.rn.f32x2 %0, %1, %2, %3;" : "=l"(d) : "l"(a), "l"(b), "l"(c));
    return d;
}
static __device__ __forceinline__ unsigned long long add2(unsigned long long a,
                                                          unsigned long long b) {
    unsigned long long d;
    asm("add.rn.f32x2 %0, %1, %2;" : "=l"(d) : "l"(a), "l"(b));
    return d;
}
static __device__ __forceinline__ unsigned long long pk2(float lo, float hi) {
    unsigned long long d;
    asm("mov.b64 %0, {%1, %2};" : "=l"(d) : "f"(lo), "f"(hi));
    return d;
}
static __device__ __forceinline__ void upk2(unsigned long long v, float& lo, float& hi) {
    asm("mov.b64 {%0, %1}, %2;" : "=f"(lo), "=f"(hi) : "l"(v));
}
static __device__ __forceinline__ unsigned su32(const void* p) {
    unsigned r;
    asm("{ .reg .u64 t; cvta.to.shared.u64 t, %1; cvt.u32.u64 %0, t; }" : "=r"(r) : "l"(p));
    return r;
}
static __device__ __forceinline__ void mbar_init(unsigned m, unsigned cnt) {
    asm volatile("mbarrier.init.shared.b64 [%0], %1;" :: "r"(m), "r"(cnt) : "memory");
}
static __device__ __forceinline__ void mbar_expect(unsigned m, unsigned bytes) {
    asm volatile("mbarrier.arrive.expect_tx.shared.b64 _, [%0], %1;" :: "r"(m), "r"(bytes) : "memory");
}
static __device__ __forceinline__ void mbar_wait(unsigned m, unsigned phase) {
    unsigned done;
    asm volatile(
        "{\n\t.reg .pred p;\n\t"
        "mbarrier.try_wait.parity.acquire.cluster.shared::cta.b64 p, [%1], %2;\n\t"
        "selp.b32 %0, 1, 0, p;\n\t}"
        : "=r"(done) : "r"(m), "r"(phase) : "memory");
    while (!done) {
        asm volatile(
            "{\n\t.reg .pred p;\n\t"
            "mbarrier.try_wait.parity.acquire.cluster.shared::cta.b64 p, [%1], %2, 0x989680;\n\t"
            "selp.b32 %0, 1, 0, p;\n\t}"
            : "=r"(done) : "r"(m), "r"(phase) : "memory");
    }
}
static __device__ __forceinline__ void st_async_b64(unsigned raddr, unsigned long long v,
                                                    unsigned rmbar) {
    asm volatile("st.async.shared::cluster.mbarrier::complete_tx::bytes.b64 [%0], %1, [%2];"
                 :: "r"(raddr), "l"(v), "r"(rmbar) : "memory");
}

// ---------------- kernel 1: build weight matrices ----------------
__global__ void prep_kernel(const float* __restrict__ C, const float* __restrict__ B) {
    int u = blockIdx.x;
    int k = threadIdx.x;
    float dg = (u == k) ? 0.01f : 0.0f;
    g_AeT[u * NU + k] = EPSF * (B[k * NU + u] - 0.6f * B[u * NU + k] - dg);
    g_WT [u * NU + k] =        (C[k * NU + u] - 0.6f * C[u * NU + k] - dg);
}

// ---------------- kernel 2: xu = X @ U + bias ----------------
__global__ __launch_bounds__(256) void xu_kernel(const float* __restrict__ X,
                                                 const float* __restrict__ U,
                                                 const float* __restrict__ bias) {
    __shared__ __align__(16) float Xs[32][132];
    __shared__ __align__(16) float Us[32][132];

    int tid = threadIdx.x;
    int m0 = blockIdx.x * 128;
    int n0 = blockIdx.y * 128;
    int tx = tid & 15;
    int ty = tid >> 4;

    unsigned long long acc[8][4];
#pragma unroll
    for (int i = 0; i < 8; i++)
#pragma unroll
        for (int j = 0; j < 4; j++) acc[i][j] = 0ULL;

    for (int kt = 0; kt < 256; kt += 32) {
#pragma unroll
        for (int i = 0; i < 4; i++) {
            int f = tid + i * 256;
            int m = f >> 3;
            int k4 = (f & 7) * 4;
            float4 v = *(const float4*)&X[(size_t)(m0 + m) * 256 + kt + k4];
            Xs[k4 + 0][m] = v.x;
            Xs[k4 + 1][m] = v.y;
            Xs[k4 + 2][m] = v.z;
            Xs[k4 + 3][m] = v.w;
        }
#pragma unroll
        for (int i = 0; i < 4; i++) {
            int f = tid + i * 256;
            int k = f >> 5;
            int n4 = (f & 31) * 4;
            float4 v = *(const float4*)&U[(size_t)(kt + k) * 256 + n0 + n4];
            *(float4*)&Us[k][n4] = v;
        }
        __syncthreads();

#pragma unroll
        for (int kk = 0; kk < 32; kk++) {
            float a[8];
            *(float4*)&a[0] = *(const float4*)&Xs[kk][ty * 8];
            *(float4*)&a[4] = *(const float4*)&Xs[kk][ty * 8 + 4];
            ulonglong2 b01 = *(const ulonglong2*)&Us[kk][tx * 8];
            ulonglong2 b23 = *(const ulonglong2*)&Us[kk][tx * 8 + 4];
#pragma unroll
            for (int mi = 0; mi < 8; mi++) {
                unsigned long long ad = pk2(a[mi], a[mi]);
                acc[mi][0] = fma2(ad, b01.x, acc[mi][0]);
                acc[mi][1] = fma2(ad, b01.y, acc[mi][1]);
                acc[mi][2] = fma2(ad, b23.x, acc[mi][2]);
                acc[mi][3] = fma2(ad, b23.y, acc[mi][3]);
            }
        }
        __syncthreads();
    }

    float bv[8];
#pragma unroll
    for (int j = 0; j < 8; j++) bv[j] = bias[n0 + tx * 8 + j];
#pragma unroll
    for (int mi = 0; mi < 8; mi++) {
        float* orow = &g_xu[(size_t)(m0 + ty * 8 + mi) * 256 + n0 + tx * 8];
#pragma unroll
        for (int ni = 0; ni < 4; ni++) {
            float lo, hi;
            upk2(acc[mi][ni], lo, hi);
            float2 v = make_float2(lo + bv[2 * ni], hi + bv[2 * ni + 1]);
            *(float2*)&orow[2 * ni] = v;
        }
    }
}

// ---------------- kernel 3: the recurrence (uniform dataflow, 1 sync/step) ----
// 32 clusters x 4 CTAs. CTA rank r owns units [64r,64r+64); weights in regs.
// h per buffer: [batch][k-pair u64] (2 KB), triple buffered, filled ONLY by
// st.async (including a self-loopback copy for the CTA's own slice). Every FMA
// warp is gated uniformly by its source rank's per-buffer mbarrier; red_s is
// step-parity double-buffered, so only ONE __syncthreads per step is needed
// (separating red_s writes from the consumer reduction).
__global__ void __launch_bounds__(512, 1) __cluster_dims__(4, 1, 1)
rec_kernel(float* __restrict__ out) {
    __shared__ __align__(16) unsigned long long h_s[3][2][128];       // 6 KB
    __shared__ __align__(16) unsigned long long red_s[2][2][4][64];   // [par][mat][ks][unit] 8 KB
    __shared__ __align__(8)  unsigned long long mbars[12];            // [buf][src]

    int tid  = threadIdx.x;
    int lane = tid & 31;
    int wid  = tid >> 5;             // 16 warps
    int mat  = wid >> 3;             // 0 = A, 1 = W
    int ks   = (wid >> 1) & 3;       // source rank of this warp's k-range
    int usub = wid & 1;
    int unit = usub * 32 + lane;     // 0..63 within CTA slice
    unsigned rank;
    asm("mov.u32 %0, %%cluster_ctarank;" : "=r"(rank));
    int bg  = (int)(blockIdx.x >> 2);
    int ug  = (int)rank * 64 + unit;
    int kp0 = ks * 32;

    bool is_armer = (mat == 0 && usub == 0 && lane == 0);   // one per source

    // Weight slice in registers as native k-pairs.
    unsigned long long wD[32];
    {
        const float* wsrc = (mat == 0) ? g_AeT : g_WT;
        const unsigned long long* wp =
            (const unsigned long long*)(wsrc + (size_t)ug * NU) + kp0;
#pragma unroll
        for (int i = 0; i < 32; i++) wD[i] = wp[i];
    }

    // Init: zero buffer 0, init per-source tx mbarriers, pre-arm bufs 1, 2
    // for ALL 4 sources (self included). 64 b64 msgs = 512 B per (buf, src).
    if (tid < 256) h_s[0][tid >> 7][tid & 127] = 0ULL;
    unsigned mb = su32(&mbars[0]);
    if (tid == 0) {
#pragma unroll
        for (int i = 0; i < 12; i++) mbar_init(mb + 8u * i, 1);
#pragma unroll
        for (int s = 0; s < 4; s++) {
            mbar_expect(mb + (1 * 4 + s) * 8u, 512);
            mbar_expect(mb + (2 * 4 + s) * 8u, 512);
        }
    }
    __syncthreads();
    asm volatile("barrier.cluster.arrive.aligned;" ::: "memory");
    asm volatile("barrier.cluster.wait.aligned;" ::: "memory");

    // Consumer identity (first 128 threads: one (batch cb, unit cu) each)
    int cb  = (tid >> 6) & 1;
    int cu  = tid & 63;
    int cug = (int)rank * 64 + cu;
    const float* xu_p = g_xu + ((size_t)(bg * 2 + cb) * TS) * NU + cug;
    float* out_p      = out  + ((size_t)(bg * 2 + cb) * TS) * NU + cug;
    unsigned pair_off = (unsigned)cb * 1024u + (unsigned)rank * 256u + (unsigned)(cu >> 1) * 8u;

    // Remote base addresses for ALL 4 cluster ranks (self included: loopback)
    unsigned ra4[4];
    unsigned h0 = su32(&h_s[0][0][0]);
    unsigned mdel = mb - h0;
#pragma unroll
    for (int r = 0; r < 4; r++) {
        asm("mapa.shared::cluster.u32 %0, %1, %2;" : "=r"(ra4[r]) : "r"(h0), "r"(r));
    }

    unsigned ph0 = 0, ph1 = 0, ph2 = 0;
    float hold = 0.0f;     // loop-carried h (consumer threads)

    // xu prefetch pipeline (consumers): xu_nxt holds xu[t] at top of step t.
    float xu_nxt = 0.0f;
    if (tid < 128) xu_nxt = __ldg(xu_p);

#define DO_STEP(RB, WB, PH, DOWAIT, T)                                              \
    {                                                                               \
        if (DOWAIT) { mbar_wait(mb + ((RB) * 4 + ks) * 8u, (PH)); }                 \
        if (is_armer) mbar_expect(mb + ((RB) * 4 + ks) * 8u, 512);                  \
        float xu_v = xu_nxt;                                                        \
        if (tid < 128 && (T) + 1 < TS)                                              \
            xu_nxt = __ldg(xu_p + (size_t)((T) + 1) * NU);                          \
        unsigned long long a00 = 0, a01 = 0, a10 = 0, a11 = 0;                      \
        {                                                                           \
            const ulonglong2* hb0 = (const ulonglong2*)&h_s[RB][0][kp0];            \
            const ulonglong2* hb1 = (const ulonglong2*)&h_s[RB][1][kp0];            \
            _Pragma("unroll")                                                       \
            for (int i = 0; i < 16; i++) {                                          \
                ulonglong2 v0 = hb0[i];                                             \
                ulonglong2 v1 = hb1[i];                                             \
                a00 = fma2(wD[2 * i + 0], v0.x, a00);                               \
                a01 = fma2(wD[2 * i + 1], v0.y, a01);                               \
                a10 = fma2(wD[2 * i + 0], v1.x, a10);                               \
                a11 = fma2(wD[2 * i + 1], v1.y, a11);                               \
            }                                                                       \
        }                                                                           \
        {                                                                           \
            unsigned long long s0 = add2(a00, a01);                                 \
            unsigned long long s1 = add2(a10, a11);                                 \
            float l0, hh0, l1, hh1;                                                 \
            upk2(s0, l0, hh0);                                                      \
            upk2(s1, l1, hh1);                                                      \
            red_s[(T) & 1][mat][ks][unit] = pk2(l0 + hh0, l1 + hh1);                \
        }                                                                           \
        __syncthreads();                                                            \
        if (tid < 128) {                                                            \
            /* W-part first so tanh starts ASAP */                                  \
            float sW = 0.0f;                                                        \
            _Pragma("unroll")                                                       \
            for (int kss = 0; kss < 4; kss++)                                       \
                sW += ((const float*)&red_s[(T) & 1][1][kss][cu])[cb];              \
            float th = tanhf(sW + xu_v);                                            \
            float sA = 0.0f;                                                        \
            _Pragma("unroll")                                                       \
            for (int kss = 0; kss < 4; kss++)                                       \
                sA += ((const float*)&red_s[(T) & 1][0][kss][cu])[cb];              \
            float hnew = hold + sA + EPSF * th;                                     \
            hold = hnew;                                                            \
            float other = __shfl_xor_sync(0xFFFFFFFFu, hnew, 1);                    \
            unsigned long long val = (cu & 1) ? pk2(other, hnew) : pk2(hnew, other);\
            unsigned doff = (unsigned)(WB) * 2048u + pair_off;                      \
            unsigned moff = mdel + ((WB) * 4 + (int)rank) * 8u;                     \
            if (!(cu & 1)) {                                                        \
                _Pragma("unroll")                                                   \
                for (int r = 0; r < 4; r++)                                         \
                    st_async_b64(ra4[r] + doff, val, ra4[r] + moff);                \
            }                                                                       \
            out_p[(size_t)(T) * NU] = hnew;                                         \
        }                                                                           \
    }

    // step 0 (reads pre-zeroed buffer 0, no wait; arms buf0's source barriers)
    DO_STEP(0, 1, ph0, false, 0);
    int t = 1;
    while (t < TS) {
        DO_STEP(1, 2, ph1, true, t); ph1 ^= 1; t++;
        if (t < TS) { DO_STEP(2, 0, ph2, true, t); ph2 ^= 1; t++; }
        if (t < TS) { DO_STEP(0, 1, ph0, true, t); ph0 ^= 1; t++; }
    }
#undef DO_STEP

    // Drain: final sends (t=2047) filled buf 2 (all 4 sources); wait so no CTA
    // exits while peers' remote stores into its smem are in flight.
    __syncthreads();
    if (tid == 0) {
#pragma unroll
        for (int s = 0; s < 4; s++) mbar_wait(mb + (2 * 4 + s) * 8u, ph2);
    }
    __syncthreads();
    asm volatile("barrier.cluster.arrive.aligned;" ::: "memory");
    asm volatile("barrier.cluster.wait.aligned;" ::: "memory");
}

extern "C" void kernel_launch(void* const* d_in, const int* in_sizes, int n_in,
                              void* d_out, int out_size) {
    const float* x = (const float*)d_in[0];
    const float* C = (const float*)d_in[1];
    const float* B = (const float*)d_in[2];
    const float* U = (const float*)d_in[3];
    const float* b = (const float*)d_in[4];
    float* out = (float*)d_out;

    prep_kernel<<<NU, NU>>>(C, B);
    xu_kernel<<<dim3((NB * TS) / 128, NU / 128), 256>>>(x, U, b);
    rec_kernel<<<128, 512>>>(out);
}

// round 14
// speedup vs baseline: 1.0802x; 1.0626x over previous
#include <cuda_runtime.h>
#include <cuda_bf16.h>
#include <cstddef>

#define EPSF 0.01f
#define NU 256
#define NB 64
#define TS 2048

// Module-load-time scratch (no runtime allocation)
__device__ float g_xu[(size_t)NB * TS * NU];   // x@U + b, [b][t][u]
__device__ float g_AeT[NU * NU];               // EPS*A, transposed
__device__ float g_WT [NU * NU];               // W, transposed

// ---------------- packed fp32x2 helpers ----------------
static __device__ __forceinline__ unsigned long long fma2(unsigned long long a,
                                                          unsigned long long b,
                                                          unsigned long long c) {
    unsigned long long d;
    asm("fma.rn.f32x2 %0, %1, %2, %3;" : "=l"(d) : "l"(a), "l"(b), "l"(c));
    return d;
}
static __device__ __forceinline__ unsigned long long add2(unsigned long long a,
                                                          unsigned long long b) {
    unsigned long long d;
    asm("add.rn.f32x2 %0, %1, %2;" : "=l"(d) : "l"(a), "l"(b));
    return d;
}
static __device__ __forceinline__ unsigned long long pk2(float lo, float hi) {
    unsigned long long d;
    asm("mov.b64 %0, {%1, %2};" : "=l"(d) : "f"(lo), "f"(hi));
    return d;
}
static __device__ __forceinline__ void upk2(unsigned long long v, float& lo, float& hi) {
    asm("mov.b64 {%0, %1}, %2;" : "=f"(lo), "=f"(hi) : "l"(v));
}
static __device__ __forceinline__ float tanh_approx(float x) {
    float y;
    asm("tanh.approx.f32 %0, %1;" : "=f"(y) : "f"(x));
    return y;
}
static __device__ __forceinline__ unsigned su32(const void* p) {
    unsigned r;
    asm("{ .reg .u64 t; cvta.to.shared.u64 t, %1; cvt.u32.u64 %0, t; }" : "=r"(r) : "l"(p));
    return r;
}
static __device__ __forceinline__ void mbar_init(unsigned m, unsigned cnt) {
    asm volatile("mbarrier.init.shared.b64 [%0], %1;" :: "r"(m), "r"(cnt) : "memory");
}
static __device__ __forceinline__ void mbar_expect(unsigned m, unsigned bytes) {
    asm volatile("mbarrier.arrive.expect_tx.shared.b64 _, [%0], %1;" :: "r"(m), "r"(bytes) : "memory");
}
static __device__ __forceinline__ void mbar_wait(unsigned m, unsigned phase) {
    unsigned done;
    asm volatile(
        "{\n\t.reg .pred p;\n\t"
        "mbarrier.try_wait.parity.acquire.cluster.shared::cta.b64 p, [%1], %2;\n\t"
        "selp.b32 %0, 1, 0, p;\n\t}"
        : "=r"(done) : "r"(m), "r"(phase) : "memory");
    while (!done) {
        asm volatile(
            "{\n\t.reg .pred p;\n\t"
            "mbarrier.try_wait.parity.acquire.cluster.shared::cta.b64 p, [%1], %2, 0x989680;\n\t"
            "selp.b32 %0, 1, 0, p;\n\t}"
            : "=r"(done) : "r"(m), "r"(phase) : "memory");
    }
}
static __device__ __forceinline__ void st_async_b64(unsigned raddr, unsigned long long v,
                                                    unsigned rmbar) {
    asm volatile("st.async.shared::cluster.mbarrier::complete_tx::bytes.b64 [%0], %1, [%2];"
                 :: "r"(raddr), "l"(v), "r"(rmbar) : "memory");
}

// ---------------- kernel 1: build weight matrices ----------------
__global__ void prep_kernel(const float* __restrict__ C, const float* __restrict__ B) {
    int u = blockIdx.x;
    int k = threadIdx.x;
    float dg = (u == k) ? 0.01f : 0.0f;
    g_AeT[u * NU + k] = EPSF * (B[k * NU + u] - 0.6f * B[u * NU + k] - dg);
    g_WT [u * NU + k] =        (C[k * NU + u] - 0.6f * C[u * NU + k] - dg);
}

// ---------------- kernel 2: xu = X @ U + bias ----------------
__global__ __launch_bounds__(256) void xu_kernel(const float* __restrict__ X,
                                                 const float* __restrict__ U,
                                                 const float* __restrict__ bias) {
    __shared__ __align__(16) float Xs[32][132];
    __shared__ __align__(16) float Us[32][132];

    int tid = threadIdx.x;
    int m0 = blockIdx.x * 128;
    int n0 = blockIdx.y * 128;
    int tx = tid & 15;
    int ty = tid >> 4;

    unsigned long long acc[8][4];
#pragma unroll
    for (int i = 0; i < 8; i++)
#pragma unroll
        for (int j = 0; j < 4; j++) acc[i][j] = 0ULL;

    for (int kt = 0; kt < 256; kt += 32) {
#pragma unroll
        for (int i = 0; i < 4; i++) {
            int f = tid + i * 256;
            int m = f >> 3;
            int k4 = (f & 7) * 4;
            float4 v = *(const float4*)&X[(size_t)(m0 + m) * 256 + kt + k4];
            Xs[k4 + 0][m] = v.x;
            Xs[k4 + 1][m] = v.y;
            Xs[k4 + 2][m] = v.z;
            Xs[k4 + 3][m] = v.w;
        }
#pragma unroll
        for (int i = 0; i < 4; i++) {
            int f = tid + i * 256;
            int k = f >> 5;
            int n4 = (f & 31) * 4;
            float4 v = *(const float4*)&U[(size_t)(kt + k) * 256 + n0 + n4];
            *(float4*)&Us[k][n4] = v;
        }
        __syncthreads();

#pragma unroll
        for (int kk = 0; kk < 32; kk++) {
            float a[8];
            *(float4*)&a[0] = *(const float4*)&Xs[kk][ty * 8];
            *(float4*)&a[4] = *(const float4*)&Xs[kk][ty * 8 + 4];
            ulonglong2 b01 = *(const ulonglong2*)&Us[kk][tx * 8];
            ulonglong2 b23 = *(const ulonglong2*)&Us[kk][tx * 8 + 4];
#pragma unroll
            for (int mi = 0; mi < 8; mi++) {
                unsigned long long ad = pk2(a[mi], a[mi]);
                acc[mi][0] = fma2(ad, b01.x, acc[mi][0]);
                acc[mi][1] = fma2(ad, b01.y, acc[mi][1]);
                acc[mi][2] = fma2(ad, b23.x, acc[mi][2]);
                acc[mi][3] = fma2(ad, b23.y, acc[mi][3]);
            }
        }
        __syncthreads();
    }

    float bv[8];
#pragma unroll
    for (int j = 0; j < 8; j++) bv[j] = bias[n0 + tx * 8 + j];
#pragma unroll
    for (int mi = 0; mi < 8; mi++) {
        float* orow = &g_xu[(size_t)(m0 + ty * 8 + mi) * 256 + n0 + tx * 8];
#pragma unroll
        for (int ni = 0; ni < 4; ni++) {
            float lo, hi;
            upk2(acc[mi][ni], lo, hi);
            float2 v = make_float2(lo + bv[2 * ni], hi + bv[2 * ni + 1]);
            *(float2*)&orow[2 * ni] = v;
        }
    }
}

// ---------------- kernel 3: the recurrence (R11 protocol + epilogue opts) ----
// 32 clusters x 4 CTAs. CTA rank r owns units [64r,64r+64); weights in regs.
// h per buffer: [batch][k-pair u64] (2 KB), triple buffered.
// PER-SOURCE tx mbarriers: mbar[buf][src]; senders target mbar[WB][own_rank];
// each FMA warp waits only its own source's barrier; ks==rank warps skip the
// wait (local STS, ordered by the top __syncthreads). Re-arm after wait.
// Epilogue: W-sum -> HW tanh.approx -> A-sum -> sends -> STG (sends early).
// red_s is conflict-free float planes [mat][ks][batch][unit].
__global__ void __launch_bounds__(512, 1) __cluster_dims__(4, 1, 1)
rec_kernel(float* __restrict__ out) {
    __shared__ __align__(16) unsigned long long h_s[3][2][128];   // [buf][b][kp] 6 KB
    __shared__ __align__(16) float red_s[2][4][2][64];            // [mat][ks][b][unit] 4 KB
    __shared__ __align__(8)  unsigned long long mbars[12];        // [buf][src]

    int tid  = threadIdx.x;
    int lane = tid & 31;
    int wid  = tid >> 5;             // 16 warps
    int mat  = wid >> 3;             // 0 = A, 1 = W
    int ks   = (wid >> 1) & 3;       // source rank of this warp's k-range
    int usub = wid & 1;
    int unit = usub * 32 + lane;     // 0..63 within CTA slice
    unsigned rank;
    asm("mov.u32 %0, %%cluster_ctarank;" : "=r"(rank));
    int bg  = (int)(blockIdx.x >> 2);
    int ug  = (int)rank * 64 + unit;
    int kp0 = ks * 32;

    bool needs_wait = (ks != (int)rank);                      // warp-uniform
    bool is_armer   = needs_wait && mat == 0 && usub == 0 && lane == 0;

    // Weight slice in registers as native k-pairs.
    unsigned long long wD[32];
    {
        const float* wsrc = (mat == 0) ? g_AeT : g_WT;
        const unsigned long long* wp =
            (const unsigned long long*)(wsrc + (size_t)ug * NU) + kp0;
#pragma unroll
        for (int i = 0; i < 32; i++) wD[i] = wp[i];
    }

    // Init: zero buffer 0, init per-source tx mbarriers, pre-arm bufs 1, 2.
    if (tid < 256) h_s[0][tid >> 7][tid & 127] = 0ULL;
    unsigned mb = su32(&mbars[0]);
    if (tid == 0) {
#pragma unroll
        for (int i = 0; i < 12; i++) mbar_init(mb + 8u * i, 1);
#pragma unroll
        for (int s = 0; s < 4; s++) {
            if (s != (int)rank) {
                mbar_expect(mb + (1 * 4 + s) * 8u, 512);
                mbar_expect(mb + (2 * 4 + s) * 8u, 512);
            }
        }
    }
    __syncthreads();
    asm volatile("barrier.cluster.arrive.aligned;" ::: "memory");
    asm volatile("barrier.cluster.wait.aligned;" ::: "memory");

    // Consumer identity (first 128 threads: one (batch cb, unit cu) each)
    int cb  = (tid >> 6) & 1;
    int cu  = tid & 63;
    int cug = (int)rank * 64 + cu;
    const float* xu_p = g_xu + ((size_t)(bg * 2 + cb) * TS) * NU + cug;
    float* out_p      = out  + ((size_t)(bg * 2 + cb) * TS) * NU + cug;
    unsigned pair_off = (unsigned)cb * 1024u + (unsigned)rank * 256u + (unsigned)(cu >> 1) * 8u;

    // Remote base addresses for the 3 OTHER cluster ranks
    unsigned ra3[3];
    unsigned h0 = su32(&h_s[0][0][0]);
    unsigned mdel = mb - h0;
    {
        int j = 0;
#pragma unroll
        for (int r = 0; r < 4; r++) {
            if (r != (int)rank) {
                asm("mapa.shared::cluster.u32 %0, %1, %2;" : "=r"(ra3[j]) : "r"(h0), "r"(r));
                j++;
            }
        }
    }

    unsigned ph0 = 0, ph1 = 0, ph2 = 0;
    float hold = 0.0f;     // loop-carried h (consumer threads)

    // xu prefetch pipeline (consumers): xu_nxt holds xu[t] at top of step t.
    float xu_nxt = 0.0f;
    if (tid < 128) xu_nxt = __ldg(xu_p);

#define DO_STEP(RB, WB, PH, DOWAIT, T)                                              \
    {                                                                               \
        /* order previous step's LOCAL STS of buf RB before this step's reads */    \
        __syncthreads();                                                            \
        if (DOWAIT && needs_wait) { mbar_wait(mb + ((RB) * 4 + ks) * 8u, (PH)); }   \
        if (is_armer) mbar_expect(mb + ((RB) * 4 + ks) * 8u, 512);                  \
        float xu_v = xu_nxt;                                                        \
        if (tid < 128 && (T) + 1 < TS)                                              \
            xu_nxt = __ldg(xu_p + (size_t)((T) + 1) * NU);                          \
        unsigned long long a00 = 0, a01 = 0, a10 = 0, a11 = 0;                      \
        {                                                                           \
            const ulonglong2* hb0 = (const ulonglong2*)&h_s[RB][0][kp0];            \
            const ulonglong2* hb1 = (const ulonglong2*)&h_s[RB][1][kp0];            \
            _Pragma("unroll")                                                       \
            for (int i = 0; i < 16; i++) {                                          \
                ulonglong2 v0 = hb0[i];                                             \
                ulonglong2 v1 = hb1[i];                                             \
                a00 = fma2(wD[2 * i + 0], v0.x, a00);                               \
                a01 = fma2(wD[2 * i + 1], v0.y, a01);                               \
                a10 = fma2(wD[2 * i + 0], v1.x, a10);                               \
                a11 = fma2(wD[2 * i + 1], v1.y, a11);                               \
            }                                                                       \
        }                                                                           \
        {                                                                           \
            unsigned long long s0 = add2(a00, a01);                                 \
            unsigned long long s1 = add2(a10, a11);                                 \
            float l0, hh0, l1, hh1;                                                 \
            upk2(s0, l0, hh0);                                                      \
            upk2(s1, l1, hh1);                                                      \
            red_s[mat][ks][0][unit] = l0 + hh0;                                     \
            red_s[mat][ks][1][unit] = l1 + hh1;                                     \
        }                                                                           \
        __syncthreads();                                                            \
        if (tid < 128) {                                                            \
            /* W-part first so tanh starts ASAP */                                  \
            float sW = (red_s[1][0][cb][cu] + red_s[1][1][cb][cu]) +                 \
                       (red_s[1][2][cb][cu] + red_s[1][3][cb][cu]);                  \
            float th = tanh_approx(sW + xu_v);                                      \
            float sA = (red_s[0][0][cb][cu] + red_s[0][1][cb][cu]) +                 \
                       (red_s[0][2][cb][cu] + red_s[0][3][cb][cu]);                  \
            float hnew = hold + sA + EPSF * th;                                     \
            hold = hnew;                                                            \
            float other = __shfl_xor_sync(0xFFFFFFFFu, hnew, 1);                    \
            unsigned long long val = (cu & 1) ? pk2(other, hnew) : pk2(hnew, other);\
            unsigned doff = (unsigned)(WB) * 2048u + pair_off;                      \
            unsigned moff = mdel + ((WB) * 4 + (int)rank) * 8u;                     \
            if (!(cu & 1)) {                                                        \
                st_async_b64(ra3[0] + doff, val, ra3[0] + moff);                    \
                st_async_b64(ra3[1] + doff, val, ra3[1] + moff);                    \
                st_async_b64(ra3[2] + doff, val, ra3[2] + moff);                    \
                h_s[WB][cb][(int)rank * 32 + (cu >> 1)] = val;  /* local STS */     \
            }                                                                       \
            out_p[(size_t)(T) * NU] = hnew;                                         \
        }                                                                           \
    }

    // step 0 (reads pre-zeroed buffer 0, no wait; arms buf0's source barriers)
    DO_STEP(0, 1, ph0, false, 0);
    int t = 1;
    while (t < TS) {
        DO_STEP(1, 2, ph1, true, t); ph1 ^= 1; t++;
        if (t < TS) { DO_STEP(2, 0, ph2, true, t); ph2 ^= 1; t++; }
        if (t < TS) { DO_STEP(0, 1, ph0, true, t); ph0 ^= 1; t++; }
    }
#undef DO_STEP

    // Drain: final sends (t=2047) filled buf 2; wait for those arrivals so no
    // CTA exits while peers' remote stores into its smem are in flight.
    if (tid == 0) {
#pragma unroll
        for (int s = 0; s < 4; s++)
            if (s != (int)rank) mbar_wait(mb + (2 * 4 + s) * 8u, ph2);
    }
    __syncthreads();
    asm volatile("barrier.cluster.arrive.aligned;" ::: "memory");
    asm volatile("barrier.cluster.wait.aligned;" ::: "memory");
}

extern "C" void kernel_launch(void* const* d_in, const int* in_sizes, int n_in,
                              void* d_out, int out_size) {
    const float* x = (const float*)d_in[0];
    const float* C = (const float*)d_in[1];
    const float* B = (const float*)d_in[2];
    const float* U = (const float*)d_in[3];
    const float* b = (const float*)d_in[4];
    float* out = (float*)d_out;

    prep_kernel<<<NU, NU>>>(C, B);
    xu_kernel<<<dim3((NB * TS) / 128, NU / 128), 256>>>(x, U, b);
    rec_kernel<<<128, 512>>>(out);
}